// round 1
// baseline (speedup 1.0000x reference)
#include <cuda_runtime.h>

#define B_  64
#define I_  2048
#define D_  16
#define J_  32
#define E_  32
#define JE_ 1024

// Scratch (static __device__ arrays — no allocation in kernel_launch).
__device__ __align__(16) float g_uhat[(size_t)B_ * I_ * JE_];  // [b][i][j*32+e], 512 MB
__device__ __align__(16) float g_s[B_ * JE_];                  // [b][j][e]
__device__ __align__(16) float g_oacc[B_ * JE_];               // accumulated outputs (for logits)

// ---------------------------------------------------------------------------
// Zero s and oacc
// ---------------------------------------------------------------------------
__global__ void init_kernel() {
    int t = blockIdx.x * blockDim.x + threadIdx.x;
    if (t < B_ * JE_) { g_s[t] = 0.f; g_oacc[t] = 0.f; }
}

// ---------------------------------------------------------------------------
// u_hat creation: one CTA per i. Per-i GEMM: X_i[64x16] * W_i[16x1024].
// W_i (64KB) staged in SMEM once, reused by all 64 batches via 8x8 register
// tiles (1 B of SMEM per FMA -> balanced against the 128B/cyc crossbar).
// ---------------------------------------------------------------------------
__global__ void __launch_bounds__(256) create_uhat_kernel(
    const float* __restrict__ x, const float* __restrict__ W) {
    extern __shared__ float4 smem[];
    float4* sW = smem;          // [dc][je] : 4 * 1024 float4 = 64 KB
    float4* sx = smem + 4096;   // [dc][b]  : 4 * 64  float4 = 4 KB

    const int i = blockIdx.x;
    const int t = threadIdx.x;
    const int l = t & 31;

    // Load W[:, i, :, :] -> SMEM [dc][j*32+e].
    // Lane-permuted r keeps global reads coalesced (warp covers 32 consecutive
    // float4) while making STS phases (8 lanes) hit distinct banks.
    const float4* Wg = (const float4*)W;
    #pragma unroll
    for (int m = 0; m < 16; m++) {
        int k = t + 256 * m;
        int j = k >> 7;                                   // 128 float4 per (j,i)
        int r = (k & 96) | ((l & 7) << 2) | (l >> 3);     // permuted e*4+dc
        float4 v = Wg[(size_t)j * (I_ * 128) + (size_t)i * 128 + r];
        sW[(r & 3) * 1024 + j * 32 + (r >> 2)] = v;
    }
    // Load x[:, i, :] -> SMEM [dc][b]
    {
        int bb = t >> 2, dc = t & 3;
        sx[dc * 64 + bb] = ((const float4*)x)[(size_t)(bb * I_ + i) * 4 + dc];
    }
    __syncthreads();

    const int tx = t & 31, ty = t >> 5;
    for (int s = 0; s < 4; s++) {                    // 4 sectors of 256 je
        float acc[8][8];
        #pragma unroll
        for (int v = 0; v < 8; v++)
            #pragma unroll
            for (int u = 0; u < 8; u++) acc[v][u] = 0.f;

        #pragma unroll
        for (int dc = 0; dc < 4; dc++) {
            float4 xr[8], wr[8];
            #pragma unroll
            for (int v = 0; v < 8; v++) xr[v] = sx[dc * 64 + ty + 8 * v];      // broadcast
            #pragma unroll
            for (int u = 0; u < 8; u++) wr[u] = sW[dc * 1024 + s * 256 + tx + 32 * u];
            #pragma unroll
            for (int v = 0; v < 8; v++)
                #pragma unroll
                for (int u = 0; u < 8; u++) {
                    acc[v][u] += xr[v].x * wr[u].x;
                    acc[v][u] += xr[v].y * wr[u].y;
                    acc[v][u] += xr[v].z * wr[u].z;
                    acc[v][u] += xr[v].w * wr[u].w;
                }
        }
        #pragma unroll
        for (int v = 0; v < 8; v++) {
            float* orow = g_uhat + ((size_t)(ty + 8 * v) * I_ + i) * JE_ + s * 256 + tx;
            #pragma unroll
            for (int u = 0; u < 8; u++) orow[32 * u] = acc[v][u];   // coalesced (tx)
        }
    }
}

// ---------------------------------------------------------------------------
// Fused routing pass: per (b,i) row held in warp registers.
//   logits[j] = sum_e oacc[b,j,e]*u_hat[b,i,j,e]   (zero oacc => uniform c)
//   c = softmax_j(logits);  s[b,j,e] += c[j]*u_hat[b,i,j,e]
// Warp lane layout per iter: 4 j's x (8 lanes/j, float4 of e each).
// ---------------------------------------------------------------------------
__global__ void __launch_bounds__(256) routing_pass_kernel() {
    __shared__ float  s_logits[8][32];
    __shared__ float4 s_part[8 * 256];     // per-warp s partials, [w][je/4]

    const int t = threadIdx.x;
    const int w = t >> 5, l = t & 31;
    const int bb = blockIdx.x >> 3;        // batch
    const int chunk = blockIdx.x & 7;      // 8 chunks of 256 i per batch
    const int g8 = l >> 3, q = l & 7;

    // Preload oacc slices matching this lane's (j,e) footprint.
    float4 oa[8];
    #pragma unroll
    for (int it = 0; it < 8; it++) {
        int j = it * 4 + g8;
        oa[it] = *(const float4*)(g_oacc + bb * JE_ + j * 32 + q * 4);
    }
    float4 acc[8];
    #pragma unroll
    for (int it = 0; it < 8; it++) acc[it] = make_float4(0.f, 0.f, 0.f, 0.f);

    const float4* ub = (const float4*)(g_uhat + ((size_t)bb * I_ + chunk * 256 + w * 32) * JE_);

    for (int row = 0; row < 32; row++) {
        const float4* u4 = ub + (size_t)row * 256;
        float4 u[8];
        #pragma unroll
        for (int it = 0; it < 8; it++) u[it] = u4[it * 32 + l];   // coalesced

        // Phase A: logits (dot over e within 8-lane groups)
        #pragma unroll
        for (int it = 0; it < 8; it++) {
            float p = oa[it].x * u[it].x + oa[it].y * u[it].y +
                      oa[it].z * u[it].z + oa[it].w * u[it].w;
            p += __shfl_xor_sync(0xffffffffu, p, 1);
            p += __shfl_xor_sync(0xffffffffu, p, 2);
            p += __shfl_xor_sync(0xffffffffu, p, 4);
            if (q == 0) s_logits[w][it * 4 + g8] = p;
        }
        __syncwarp();
        float lg = s_logits[w][l];
        float mx = lg;
        #pragma unroll
        for (int msk = 16; msk >= 1; msk >>= 1)
            mx = fmaxf(mx, __shfl_xor_sync(0xffffffffu, mx, msk));
        float ex = __expf(lg - mx);
        float sm = ex;
        #pragma unroll
        for (int msk = 16; msk >= 1; msk >>= 1)
            sm += __shfl_xor_sync(0xffffffffu, sm, msk);
        float c = __fdividef(ex, sm);   // lane l holds c[j = l]

        // Phase B: weighted accumulation into per-lane s partials
        #pragma unroll
        for (int it = 0; it < 8; it++) {
            float cj = __shfl_sync(0xffffffffu, c, it * 4 + g8);
            acc[it].x += cj * u[it].x;
            acc[it].y += cj * u[it].y;
            acc[it].z += cj * u[it].z;
            acc[it].w += cj * u[it].w;
        }
        __syncwarp();   // protect s_logits rewrite next row
    }

    // Per-warp partials -> SMEM -> CTA reduce -> 1024 global atomics
    #pragma unroll
    for (int it = 0; it < 8; it++)
        s_part[w * 256 + (it * 4 + g8) * 8 + q] = acc[it];
    __syncthreads();

    float4 sum = s_part[t];
    #pragma unroll
    for (int w2 = 1; w2 < 8; w2++) {
        float4 v = s_part[w2 * 256 + t];
        sum.x += v.x; sum.y += v.y; sum.z += v.z; sum.w += v.w;
    }
    float* sg = g_s + bb * JE_ + t * 4;
    atomicAdd(sg + 0, sum.x);
    atomicAdd(sg + 1, sum.y);
    atomicAdd(sg + 2, sum.z);
    atomicAdd(sg + 3, sum.w);
}

// ---------------------------------------------------------------------------
// squash(s): one block per batch; warp == one j (lanes = e).
// Non-final: oacc += o, s = 0 (ready for next pass). Final: write d_out.
// ---------------------------------------------------------------------------
__global__ void squash_kernel(float* __restrict__ out, int final_r) {
    const int bb = blockIdx.x;
    const int t = threadIdx.x;   // 1024: j = t>>5, e = t&31
    float s = g_s[bb * JE_ + t];
    float sq = s * s;
    #pragma unroll
    for (int msk = 16; msk >= 1; msk >>= 1)
        sq += __shfl_xor_sync(0xffffffffu, sq, msk);
    float scale = sq / ((1.f + sq) * sqrtf(sq + 1e-7f));
    float o = scale * s;
    if (final_r) {
        out[bb * JE_ + t] = o;
    } else {
        g_oacc[bb * JE_ + t] += o;
        g_s[bb * JE_ + t] = 0.f;
    }
}

// ---------------------------------------------------------------------------
extern "C" void kernel_launch(void* const* d_in, const int* in_sizes, int n_in,
                              void* d_out, int out_size) {
    const float* x = (const float*)d_in[0];
    const float* W = (const float*)d_in[1];
    if (in_sizes[0] != B_ * I_ * D_) {  // defensive: identify by size
        x = (const float*)d_in[1];
        W = (const float*)d_in[0];
    }

    cudaFuncSetAttribute(create_uhat_kernel,
                         cudaFuncAttributeMaxDynamicSharedMemorySize, 72 * 1024);

    init_kernel<<<64, 1024>>>();
    create_uhat_kernel<<<2048, 256, (4096 + 256) * sizeof(float4)>>>(x, W);
    for (int r = 0; r < 3; r++) {
        routing_pass_kernel<<<512, 256>>>();
        squash_kernel<<<64, 1024>>>((float*)d_out, r == 2 ? 1 : 0);
    }
}

// round 2
// speedup vs baseline: 1.2028x; 1.2028x over previous
#include <cuda_runtime.h>
#include <cuda_fp16.h>

#define B_  64
#define I_  2048
#define D_  16
#define J_  32
#define E_  32
#define JE_ 1024
#define W_ROW 512   // half2 words per (b,i) row

// Scratch (static __device__ arrays — no allocation in kernel_launch).
// u_hat stored as half2: word index w in [0,512): s=w>>7, p=(w>>5)&3, e=w&31
//   lo half = u_hat[b][i][j = s*8+2p][e], hi half = u_hat[b][i][j = s*8+2p+1][e]
__device__ __align__(16) __half2 g_uhat[(size_t)B_ * I_ * W_ROW];  // 268 MB
__device__ __align__(16) float g_s[B_ * JE_];
__device__ __align__(16) float g_oacc[B_ * JE_];

// ---------------------------------------------------------------------------
// packed fp32x2 helpers (SASS FFMA2 — only reachable via PTX fma.rn.f32x2)
// ---------------------------------------------------------------------------
__device__ __forceinline__ unsigned long long pk2(float a, float b) {
    unsigned long long r;
    asm("mov.b64 %0, {%1, %2};" : "=l"(r) : "f"(a), "f"(b));
    return r;
}
__device__ __forceinline__ void fma2(unsigned long long& d,
                                     unsigned long long a, unsigned long long b) {
    asm("fma.rn.f32x2 %0, %1, %2, %0;" : "+l"(d) : "l"(a), "l"(b));
}
__device__ __forceinline__ float2 upk(unsigned long long v) {
    float2 r;
    asm("mov.b64 {%0, %1}, %2;" : "=f"(r.x), "=f"(r.y) : "l"(v));
    return r;
}

// ---------------------------------------------------------------------------
__global__ void init_kernel() {
    int t = blockIdx.x * blockDim.x + threadIdx.x;
    if (t < B_ * JE_) { g_s[t] = 0.f; g_oacc[t] = 0.f; }
}

// ---------------------------------------------------------------------------
// u_hat creation: one CTA per i. Per-i GEMM: X_i[64x16] * W_i[16x1024].
// W_i (64KB) staged in SMEM once, reused across all 64 batches.
// Math in packed f32x2 (pairs across u => adjacent j), output fp16 half2.
// ---------------------------------------------------------------------------
__global__ void __launch_bounds__(256, 1) create_uhat_kernel(
    const float* __restrict__ x, const float* __restrict__ W) {
    extern __shared__ float4 smem[];
    float4* sW = smem;          // [dc][je]: 4*1024 float4 = 64 KB
    float4* sx = smem + 4096;   // [dc][b] : 4*64 float4 = 4 KB

    const int i = blockIdx.x;
    const int t = threadIdx.x;
    const int l = t & 31;

    // Load W[:, i, :, :] -> SMEM [dc][j*32+e] (lane-permuted: coalesced LDG,
    // conflict-free STS).
    const float4* Wg = (const float4*)W;
    #pragma unroll
    for (int m = 0; m < 16; m++) {
        int k = t + 256 * m;
        int j = k >> 7;
        int r = (k & 96) | ((l & 7) << 2) | (l >> 3);
        float4 v = Wg[(size_t)j * (I_ * 128) + (size_t)i * 128 + r];
        sW[(r & 3) * 1024 + j * 32 + (r >> 2)] = v;
    }
    {
        int bb = t >> 2, dc = t & 3;
        sx[dc * 64 + bb] = ((const float4*)x)[(size_t)(bb * I_ + i) * 4 + dc];
    }
    __syncthreads();

    const int tx = t & 31, ty = t >> 5;
    for (int s = 0; s < 4; s++) {
        unsigned long long acc2[8][4];
        #pragma unroll
        for (int v = 0; v < 8; v++)
            #pragma unroll
            for (int p = 0; p < 4; p++) acc2[v][p] = 0ull;

        #pragma unroll
        for (int dc = 0; dc < 4; dc++) {
            float xc[8][4], wc[8][4];
            #pragma unroll
            for (int v = 0; v < 8; v++) {
                float4 tv = sx[dc * 64 + ty + 8 * v];
                xc[v][0] = tv.x; xc[v][1] = tv.y; xc[v][2] = tv.z; xc[v][3] = tv.w;
            }
            #pragma unroll
            for (int u = 0; u < 8; u++) {
                float4 tw = sW[dc * 1024 + s * 256 + tx + 32 * u];
                wc[u][0] = tw.x; wc[u][1] = tw.y; wc[u][2] = tw.z; wc[u][3] = tw.w;
            }
            #pragma unroll
            for (int c = 0; c < 4; c++) {
                unsigned long long wp[4];
                #pragma unroll
                for (int p = 0; p < 4; p++)
                    wp[p] = pk2(wc[2 * p][c], wc[2 * p + 1][c]);
                #pragma unroll
                for (int v = 0; v < 8; v++) {
                    unsigned long long xd = pk2(xc[v][c], xc[v][c]);
                    #pragma unroll
                    for (int p = 0; p < 4; p++) fma2(acc2[v][p], xd, wp[p]);
                }
            }
        }
        // Store: lo = j=s*8+2p, hi = j+1, e = tx. Word = s*128 + p*32 + tx.
        #pragma unroll
        for (int v = 0; v < 8; v++) {
            __half2* outp = g_uhat + ((size_t)(ty + 8 * v) * I_ + i) * W_ROW
                          + s * 128 + tx;
            #pragma unroll
            for (int p = 0; p < 4; p++) {
                float2 f = upk(acc2[v][p]);
                outp[p * 32] = __floats2half2_rn(f.x, f.y);   // coalesced STG.32
            }
        }
    }
}

// ---------------------------------------------------------------------------
// Fused routing pass on fp16 u_hat. Warp per 32 rows; per row:
//   logits[j] = oacc[b,j,:]·u_hat[b,i,j,:]; c = softmax_j; s += c[j]*u_hat
// Lane map per uint4 (it=0..3): j_lo = it*8 + 2*(l>>3), j_hi = j_lo+1,
//   e = 4*(l&7) + k (k=0..3 within the uint4).
// ---------------------------------------------------------------------------
__global__ void __launch_bounds__(256) routing_pass_kernel() {
    __shared__ float  s_logits[8][32];
    __shared__ float4 s_part[8 * 256];

    const int t = threadIdx.x;
    const int w = t >> 5, l = t & 31;
    const int bb = blockIdx.x >> 3;
    const int chunk = blockIdx.x & 7;
    const int g = l >> 3, q = l & 7;

    float4 oaL[4], oaH[4];
    #pragma unroll
    for (int it = 0; it < 4; it++) {
        int j = it * 8 + 2 * g;
        oaL[it] = *(const float4*)(g_oacc + bb * JE_ + j * 32 + q * 4);
        oaH[it] = *(const float4*)(g_oacc + bb * JE_ + (j + 1) * 32 + q * 4);
    }
    float accL[4][4], accH[4][4];
    #pragma unroll
    for (int it = 0; it < 4; it++)
        #pragma unroll
        for (int k = 0; k < 4; k++) { accL[it][k] = 0.f; accH[it][k] = 0.f; }

    const uint4* ub = (const uint4*)g_uhat
                    + ((size_t)bb * I_ + chunk * 256 + w * 32) * 128;

    for (int row = 0; row < 32; row++) {
        const uint4* rp = ub + (size_t)row * 128;
        uint4 qd[4];
        #pragma unroll
        for (int it = 0; it < 4; it++) qd[it] = rp[it * 32 + l];  // coalesced 512B

        float2 fr[4][4];
        #pragma unroll
        for (int it = 0; it < 4; it++) {
            const __half2* h = (const __half2*)&qd[it];
            #pragma unroll
            for (int k = 0; k < 4; k++) fr[it][k] = __half22float2(h[k]);
        }

        // Phase A: logits
        #pragma unroll
        for (int it = 0; it < 4; it++) {
            float pl = oaL[it].x * fr[it][0].x + oaL[it].y * fr[it][1].x
                     + oaL[it].z * fr[it][2].x + oaL[it].w * fr[it][3].x;
            float ph = oaH[it].x * fr[it][0].y + oaH[it].y * fr[it][1].y
                     + oaH[it].z * fr[it][2].y + oaH[it].w * fr[it][3].y;
            #pragma unroll
            for (int m = 1; m <= 4; m <<= 1) {
                pl += __shfl_xor_sync(0xffffffffu, pl, m);
                ph += __shfl_xor_sync(0xffffffffu, ph, m);
            }
            if (q == 0) {
                s_logits[w][it * 8 + 2 * g]     = pl;
                s_logits[w][it * 8 + 2 * g + 1] = ph;
            }
        }
        __syncwarp();
        float lg = s_logits[w][l];       // lane l holds logit of j = l
        float mx = lg;
        #pragma unroll
        for (int m = 16; m >= 1; m >>= 1)
            mx = fmaxf(mx, __shfl_xor_sync(0xffffffffu, mx, m));
        float ex = __expf(lg - mx);
        float sm = ex;
        #pragma unroll
        for (int m = 16; m >= 1; m >>= 1)
            sm += __shfl_xor_sync(0xffffffffu, sm, m);
        float c = __fdividef(ex, sm);

        // Phase B: weighted accumulation
        #pragma unroll
        for (int it = 0; it < 4; it++) {
            float cl = __shfl_sync(0xffffffffu, c, it * 8 + 2 * g);
            float ch = __shfl_sync(0xffffffffu, c, it * 8 + 2 * g + 1);
            #pragma unroll
            for (int k = 0; k < 4; k++) {
                accL[it][k] += cl * fr[it][k].x;
                accH[it][k] += ch * fr[it][k].y;
            }
        }
        __syncwarp();
    }

    // Per-warp partials -> SMEM -> CTA reduce -> 1024 global atomics
    #pragma unroll
    for (int it = 0; it < 4; it++) {
        int j = it * 8 + 2 * g;
        s_part[w * 256 + j * 8 + q] =
            make_float4(accL[it][0], accL[it][1], accL[it][2], accL[it][3]);
        s_part[w * 256 + (j + 1) * 8 + q] =
            make_float4(accH[it][0], accH[it][1], accH[it][2], accH[it][3]);
    }
    __syncthreads();

    float4 sum = s_part[t];
    #pragma unroll
    for (int w2 = 1; w2 < 8; w2++) {
        float4 v = s_part[w2 * 256 + t];
        sum.x += v.x; sum.y += v.y; sum.z += v.z; sum.w += v.w;
    }
    float* sg = g_s + bb * JE_ + t * 4;
    atomicAdd(sg + 0, sum.x);
    atomicAdd(sg + 1, sum.y);
    atomicAdd(sg + 2, sum.z);
    atomicAdd(sg + 3, sum.w);
}

// ---------------------------------------------------------------------------
__global__ void squash_kernel(float* __restrict__ out, int final_r) {
    const int bb = blockIdx.x;
    const int t = threadIdx.x;   // j = t>>5, e = t&31
    float s = g_s[bb * JE_ + t];
    float sq = s * s;
    #pragma unroll
    for (int m = 16; m >= 1; m >>= 1)
        sq += __shfl_xor_sync(0xffffffffu, sq, m);
    float scale = sq / ((1.f + sq) * sqrtf(sq + 1e-7f));
    float o = scale * s;
    if (final_r) {
        out[bb * JE_ + t] = o;
    } else {
        g_oacc[bb * JE_ + t] += o;
        g_s[bb * JE_ + t] = 0.f;
    }
}

// ---------------------------------------------------------------------------
extern "C" void kernel_launch(void* const* d_in, const int* in_sizes, int n_in,
                              void* d_out, int out_size) {
    const float* x = (const float*)d_in[0];
    const float* W = (const float*)d_in[1];
    if (in_sizes[0] != B_ * I_ * D_) {
        x = (const float*)d_in[1];
        W = (const float*)d_in[0];
    }

    cudaFuncSetAttribute(create_uhat_kernel,
                         cudaFuncAttributeMaxDynamicSharedMemorySize, 72 * 1024);

    init_kernel<<<64, 1024>>>();
    create_uhat_kernel<<<2048, 256, (4096 + 256) * sizeof(float4)>>>(x, W);
    for (int r = 0; r < 3; r++) {
        routing_pass_kernel<<<512, 256>>>();
        squash_kernel<<<64, 1024>>>((float*)d_out, r == 2 ? 1 : 0);
    }
}

// round 3
// speedup vs baseline: 1.2521x; 1.0409x over previous
#include <cuda_runtime.h>
#include <cuda_fp16.h>

#define B_  64
#define I_  2048
#define D_  16
#define J_  32
#define E_  32
#define JE_ 1024

// u_hat: plain [b][i][j][e] fp16, half2 pairs over e. Row = 512 half2 = 2KB.
__device__ __align__(16) __half2 g_uhat[(size_t)B_ * I_ * 512];  // 268 MB
__device__ __align__(16) float g_s[B_ * JE_];
__device__ __align__(16) float g_oacc[B_ * JE_];

// ---------------------------------------------------------------------------
// packed fp32x2 helpers (SASS FFMA2 — only reachable via PTX fma.rn.f32x2)
// ---------------------------------------------------------------------------
__device__ __forceinline__ unsigned long long pk2(float a, float b) {
    unsigned long long r;
    asm("mov.b64 %0, {%1, %2};" : "=l"(r) : "f"(a), "f"(b));
    return r;
}
__device__ __forceinline__ void fma2(unsigned long long& d,
                                     unsigned long long a, unsigned long long b) {
    asm("fma.rn.f32x2 %0, %1, %2, %0;" : "+l"(d) : "l"(a), "l"(b));
}
__device__ __forceinline__ float2 upk(unsigned long long v) {
    float2 r;
    asm("mov.b64 {%0, %1}, %2;" : "=f"(r.x), "=f"(r.y) : "l"(v));
    return r;
}

// ---------------------------------------------------------------------------
__global__ void init_kernel() {
    int t = blockIdx.x * blockDim.x + threadIdx.x;
    if (t < B_ * JE_) { g_s[t] = 0.f; g_oacc[t] = 0.f; }
}

// ---------------------------------------------------------------------------
// u_hat creation: one CTA per i. X_i[64x16] * W_i[16x1024], W_i staged in SMEM.
// Math in packed f32x2; epilogue lane-pair shfl+pack emits [j][e] fp16 rows.
// ---------------------------------------------------------------------------
__global__ void __launch_bounds__(256, 1) create_uhat_kernel(
    const float* __restrict__ x, const float* __restrict__ W) {
    extern __shared__ float4 smem[];
    float4* sW = smem;          // [dc][je]: 64 KB
    float4* sx = smem + 4096;   // [dc][b] : 4 KB

    const int i = blockIdx.x;
    const int t = threadIdx.x;
    const int l = t & 31;

    const float4* Wg = (const float4*)W;
    #pragma unroll
    for (int m = 0; m < 16; m++) {
        int k = t + 256 * m;
        int j = k >> 7;
        int r = (k & 96) | ((l & 7) << 2) | (l >> 3);
        float4 v = Wg[(size_t)j * (I_ * 128) + (size_t)i * 128 + r];
        sW[(r & 3) * 1024 + j * 32 + (r >> 2)] = v;
    }
    {
        int bb = t >> 2, dc = t & 3;
        sx[dc * 64 + bb] = ((const float4*)x)[(size_t)(bb * I_ + i) * 4 + dc];
    }
    __syncthreads();

    const int tx = t & 31, ty = t >> 5;   // tx = e
    const int odd = tx & 1;
    for (int s = 0; s < 4; s++) {
        unsigned long long acc2[8][4];    // [v][p]: pair (j=s*8+2p, j+1), e=tx
        #pragma unroll
        for (int v = 0; v < 8; v++)
            #pragma unroll
            for (int p = 0; p < 4; p++) acc2[v][p] = 0ull;

        #pragma unroll
        for (int dc = 0; dc < 4; dc++) {
            float xc[8][4], wc[8][4];
            #pragma unroll
            for (int v = 0; v < 8; v++) {
                float4 tv = sx[dc * 64 + ty + 8 * v];
                xc[v][0] = tv.x; xc[v][1] = tv.y; xc[v][2] = tv.z; xc[v][3] = tv.w;
            }
            #pragma unroll
            for (int u = 0; u < 8; u++) {
                float4 tw = sW[dc * 1024 + s * 256 + tx + 32 * u];
                wc[u][0] = tw.x; wc[u][1] = tw.y; wc[u][2] = tw.z; wc[u][3] = tw.w;
            }
            #pragma unroll
            for (int c = 0; c < 4; c++) {
                unsigned long long wp[4];
                #pragma unroll
                for (int p = 0; p < 4; p++)
                    wp[p] = pk2(wc[2 * p][c], wc[2 * p + 1][c]);
                #pragma unroll
                for (int v = 0; v < 8; v++) {
                    unsigned long long xd = pk2(xc[v][c], xc[v][c]);
                    #pragma unroll
                    for (int p = 0; p < 4; p++) fma2(acc2[v][p], xd, wp[p]);
                }
            }
        }
        // Epilogue: lane pair (e=2m, 2m+1) exchange -> half2, 64B-coalesced STG.
        #pragma unroll
        for (int v = 0; v < 8; v++) {
            __half2* base = g_uhat + ((size_t)(ty + 8 * v) * I_ + i) * 512;
            #pragma unroll
            for (int p = 0; p < 4; p++) {
                float2 f = upk(acc2[v][p]);         // f.x: j0, f.y: j0+1 @ e=tx
                float send = odd ? f.x : f.y;
                float rcv = __shfl_xor_sync(0xffffffffu, send, 1);
                __half2 h = odd ? __floats2half2_rn(rcv, f.y)
                                : __floats2half2_rn(f.x, rcv);
                int j = s * 8 + 2 * p + odd;        // even lanes: j0, odd: j0+1
                base[j * 16 + (tx >> 1)] = h;
            }
        }
    }
}

// ---------------------------------------------------------------------------
// Fused routing pass, lane = j. Warp handles 32 (b,i) rows; per row:
//   logit[j] = oacc[b,j,:]·u[b,i,j,:]  (in-lane, packed f32x2)
//   c = softmax over lanes;  acc[j,:] += c * u[b,i,j,:]  (in-lane)
// uniform=1 (pass 0): c = 1/32, skip Phase A (bit-identical to softmax of 0s).
// ---------------------------------------------------------------------------
__global__ void __launch_bounds__(128) routing_pass_kernel(int uniform) {
    __shared__ float s_part[4 * 1024];

    const int t = threadIdx.x;
    const int w = t >> 5, l = t & 31;
    const int bb = blockIdx.x >> 4;
    const int chunk = blockIdx.x & 15;     // 16 chunks of 128 i

    unsigned long long oa2[16];
    if (!uniform) {
        const float4* op = (const float4*)(g_oacc + bb * JE_ + l * 32);
        #pragma unroll
        for (int k4 = 0; k4 < 8; k4++) {
            float4 v = op[k4];
            oa2[2 * k4]     = pk2(v.x, v.y);
            oa2[2 * k4 + 1] = pk2(v.z, v.w);
        }
    }
    unsigned long long acc2[16];
    #pragma unroll
    for (int k = 0; k < 16; k++) acc2[k] = 0ull;

    const uint4* ub = (const uint4*)g_uhat
        + (((size_t)bb * I_ + chunk * 128 + w * 32) * 32 + l) * 4;
    // row stride = 128 uint4

    uint4 q0 = ub[0], q1 = ub[1], q2 = ub[2], q3 = ub[3];

    #pragma unroll 4
    for (int row = 0; row < 32; row++) {
        const uint4* np = ub + (size_t)(row < 31 ? row + 1 : 31) * 128;
        uint4 n0 = np[0], n1 = np[1], n2 = np[2], n3 = np[3];

        // unpack row -> 16 packed f32x2
        unsigned long long u2[16];
        {
            const __half2* h0 = (const __half2*)&q0;
            const __half2* h1 = (const __half2*)&q1;
            const __half2* h2 = (const __half2*)&q2;
            const __half2* h3 = (const __half2*)&q3;
            #pragma unroll
            for (int k = 0; k < 4; k++) {
                float2 f;
                f = __half22float2(h0[k]); u2[k]      = pk2(f.x, f.y);
                f = __half22float2(h1[k]); u2[4 + k]  = pk2(f.x, f.y);
                f = __half22float2(h2[k]); u2[8 + k]  = pk2(f.x, f.y);
                f = __half22float2(h3[k]); u2[12 + k] = pk2(f.x, f.y);
            }
        }

        float c;
        if (uniform) {
            c = 0.03125f;
        } else {
            unsigned long long lg2 = 0ull;
            #pragma unroll
            for (int k = 0; k < 16; k++) fma2(lg2, oa2[k], u2[k]);
            float2 lf = upk(lg2);
            float lg = lf.x + lf.y;
            float mx = lg;
            #pragma unroll
            for (int m = 16; m >= 1; m >>= 1)
                mx = fmaxf(mx, __shfl_xor_sync(0xffffffffu, mx, m));
            float ex = __expf(lg - mx);
            float sm = ex;
            #pragma unroll
            for (int m = 16; m >= 1; m >>= 1)
                sm += __shfl_xor_sync(0xffffffffu, sm, m);
            c = __fdividef(ex, sm);
        }
        unsigned long long c2 = pk2(c, c);
        #pragma unroll
        for (int k = 0; k < 16; k++) fma2(acc2[k], c2, u2[k]);

        q0 = n0; q1 = n1; q2 = n2; q3 = n3;
    }

    // Per-warp partials -> swizzled SMEM -> CTA reduce -> atomics
    #pragma unroll
    for (int k4 = 0; k4 < 8; k4++) {
        int phys = (k4 + l) & 7;
        float2 a = upk(acc2[2 * k4]), b = upk(acc2[2 * k4 + 1]);
        *(float4*)&s_part[w * 1024 + l * 32 + phys * 4] =
            make_float4(a.x, a.y, b.x, b.y);
    }
    __syncthreads();

    const int j = t >> 2;
    #pragma unroll
    for (int h = 0; h < 2; h++) {
        int k4 = (t & 3) * 2 + h;
        int phys = (k4 + j) & 7;
        float4 sum = *(const float4*)&s_part[j * 32 + phys * 4];
        #pragma unroll
        for (int w2 = 1; w2 < 4; w2++) {
            float4 v = *(const float4*)&s_part[w2 * 1024 + j * 32 + phys * 4];
            sum.x += v.x; sum.y += v.y; sum.z += v.z; sum.w += v.w;
        }
        float* sg = g_s + bb * JE_ + j * 32 + k4 * 4;
        atomicAdd(sg + 0, sum.x);
        atomicAdd(sg + 1, sum.y);
        atomicAdd(sg + 2, sum.z);
        atomicAdd(sg + 3, sum.w);
    }
}

// ---------------------------------------------------------------------------
__global__ void squash_kernel(float* __restrict__ out, int final_r) {
    const int bb = blockIdx.x;
    const int t = threadIdx.x;   // j = t>>5, e = t&31
    float s = g_s[bb * JE_ + t];
    float sq = s * s;
    #pragma unroll
    for (int m = 16; m >= 1; m >>= 1)
        sq += __shfl_xor_sync(0xffffffffu, sq, m);
    float scale = sq / ((1.f + sq) * sqrtf(sq + 1e-7f));
    float o = scale * s;
    if (final_r) {
        out[bb * JE_ + t] = o;
    } else {
        g_oacc[bb * JE_ + t] += o;
        g_s[bb * JE_ + t] = 0.f;
    }
}

// ---------------------------------------------------------------------------
extern "C" void kernel_launch(void* const* d_in, const int* in_sizes, int n_in,
                              void* d_out, int out_size) {
    const float* x = (const float*)d_in[0];
    const float* W = (const float*)d_in[1];
    if (in_sizes[0] != B_ * I_ * D_) {
        x = (const float*)d_in[1];
        W = (const float*)d_in[0];
    }

    cudaFuncSetAttribute(create_uhat_kernel,
                         cudaFuncAttributeMaxDynamicSharedMemorySize, 72 * 1024);

    init_kernel<<<64, 1024>>>();
    create_uhat_kernel<<<2048, 256, (4096 + 256) * sizeof(float4)>>>(x, W);
    for (int r = 0; r < 3; r++) {
        routing_pass_kernel<<<1024, 128>>>(r == 0 ? 1 : 0);
        squash_kernel<<<64, 1024>>>((float*)d_out, r == 2 ? 1 : 0);
    }
}